// round 16
// baseline (speedup 1.0000x reference)
#include <cuda_runtime.h>
#include <cuda_bf16.h>
#include <cstdint>

#define NODES  50000
#define NEDGES 600000
#define DD     128
#define BM     128
#define BN_EPS 1e-5f
#define NBLK   ((NODES + 255) / 256)   // 196

// ---------------- scratch (no allocations allowed) ----------------
__device__ __align__(16) float g_agg[NODES * DD];
__device__ __align__(16) float g_gX[NODES * DD];
__device__ int      g_degout[NODES];
__device__ int      g_degin[NODES];
__device__ int      g_rowptr[NODES];
__device__ int      g_cursor[NODES];
__device__ int      g_esrc[NEDGES];
__device__ unsigned g_scanst[NBLK];
__device__ float    g_nsrc[NODES];
__device__ float    g_ndst[NODES];
__device__ float    g_sum[DD];
__device__ float    g_sumsq[DD];
// pre-split B matrices, n-major: [mat][n*64 + k2] packed bf16x2 (lo half = k-even)
__device__ __align__(16) uint32_t g_bhi[2][8192];
__device__ __align__(16) uint32_t g_blo[2][8192];

// ---------------- bf16 split helpers ----------------
__device__ __forceinline__ uint32_t bf16_hi_bits(float x) {
    uint32_t b = __float_as_uint(x);
    return (b + 0x7FFFu + ((b >> 16) & 1u)) & 0xFFFF0000u;
}
__device__ __forceinline__ void bpack(float ve, float vo, uint32_t& whi, uint32_t& wlo) {
    uint32_t he = bf16_hi_bits(ve), ho = bf16_hi_bits(vo);
    float re = ve - __uint_as_float(he);
    float ro = vo - __uint_as_float(ho);
    uint32_t le = bf16_hi_bits(re), lo = bf16_hi_bits(ro);
    whi = ho | (he >> 16);
    wlo = lo | (le >> 16);
}

__device__ __forceinline__ void mma_bf16(float* d, const uint32_t* a, const uint32_t* b) {
    asm volatile("mma.sync.aligned.m16n8k16.row.col.f32.bf16.bf16.f32 "
        "{%0,%1,%2,%3}, {%4,%5,%6,%7}, {%8,%9}, {%0,%1,%2,%3};"
        : "+f"(d[0]), "+f"(d[1]), "+f"(d[2]), "+f"(d[3])
        : "r"(a[0]), "r"(a[1]), "r"(a[2]), "r"(a[3]), "r"(b[0]), "r"(b[1]));
}

#define LDSM_X4(r0, r1, r2, r3, addr)                                      \
    asm volatile("ldmatrix.sync.aligned.m8n8.x4.shared.b16 {%0,%1,%2,%3}, [%4];" \
        : "=r"(r0), "=r"(r1), "=r"(r2), "=r"(r3) : "r"(addr))

// warp-inclusive scan
__device__ __forceinline__ int wscan(int v, int lane) {
    #pragma unroll
    for (int off = 1; off < 32; off <<= 1) {
        int u = __shfl_up_sync(0xFFFFFFFF, v, off);
        if (lane >= off) v += u;
    }
    return v;
}

// smem word offsets (GEMM kernel)
#define BPAD2 68
#define APADW 20
#define KSTR  132
#define W_BHI 0
#define W_BLO 8704             // 128*68
#define W_A0  17408
#define ABUF_W 5120
#define W_KEEP 27648
#define SMEM_WORDS 44544
#define SMEM_BYTES (SMEM_WORDS * 4)   // 178176

// ---------------- kernel 0: init scratch + pre-split B (n-major) ----------------
__global__ void k_initprep(const float* __restrict__ W, const float* __restrict__ Wres) {
    int b = blockIdx.x;
    int t = threadIdx.x;
    if (b == 0 && t < NBLK) g_scanst[t] = 0u;
    if (b < 49) {
        int i = b * 256 + t;
        if (i < NODES / 4) {
            ((int4*)g_degout)[i] = make_int4(0, 0, 0, 0);
            ((int4*)g_degin)[i]  = make_int4(0, 0, 0, 0);
        }
        if (i < DD) { g_sum[i] = 0.f; g_sumsq[i] = 0.f; }
    } else {
        int idx = (b - 49) * 256 + t;       // 0..16383
        int mat = idx >> 13;
        int r = idx & 8191;
        int n = r >> 6, k2 = r & 63;
        const float* B = mat ? W : Wres;
        float ve = __ldg(B + (size_t)(2 * k2) * DD + n);
        float vo = __ldg(B + (size_t)(2 * k2 + 1) * DD + n);
        uint32_t h, l;
        bpack(ve, vo, h, l);
        g_bhi[mat][r] = h;     // [n][k2] layout
        g_blo[mat][r] = l;
    }
}

// ---------------- kernel 1: degrees (4 edges/thread) ----------------
__global__ void k_deg(const int* __restrict__ src, const int* __restrict__ dst) {
    int idx = blockIdx.x * blockDim.x + threadIdx.x;
    if (idx < NEDGES / 4) {
        int4 s = __ldg((const int4*)src + idx);
        int4 d = __ldg((const int4*)dst + idx);
        atomicAdd(&g_degout[s.x], 1);
        atomicAdd(&g_degout[s.y], 1);
        atomicAdd(&g_degout[s.z], 1);
        atomicAdd(&g_degout[s.w], 1);
        atomicAdd(&g_degin[d.x], 1);
        atomicAdd(&g_degin[d.y], 1);
        atomicAdd(&g_degin[d.z], 1);
        atomicAdd(&g_degin[d.w], 1);
    }
}

// ---------------- kernel 2: single-pass decoupled-lookback scan ----------------
__global__ void k_scan() {
    __shared__ int ws[8];
    __shared__ int sh_excl;
    int t = threadIdx.x, lane = t & 31, wid = t >> 5, b = blockIdx.x;
    int i = b * 256 + t;
    int d = (i < NODES) ? g_degin[i] : 0;
    int w = wscan(d, lane);
    if (lane == 31) ws[wid] = w;
    __syncthreads();
    if (wid == 0) {
        int s = (lane < 8) ? ws[lane] : 0;
        int sw = wscan(s, lane);
        if (lane < 8) ws[lane] = sw;
    }
    __syncthreads();
    int incl = w + (wid ? ws[wid - 1] : 0);
    int bsum = ws[7];

    if (t == 0) {
        int excl = 0;
        if (b == 0) {
            atomicExch(&g_scanst[0], 0x80000000u | (unsigned)bsum);
        } else {
            atomicExch(&g_scanst[b], 0x40000000u | (unsigned)bsum);
            int j = b - 1;
            while (1) {
                unsigned v = atomicAdd(&g_scanst[j], 0u);
                if (v == 0u) continue;
                excl += (int)(v & 0x3FFFFFFFu);
                if (v & 0x80000000u) break;
                j--;
            }
            atomicExch(&g_scanst[b], 0x80000000u | (unsigned)(excl + bsum));
        }
        sh_excl = excl;
    }
    __syncthreads();
    int blkoff = sh_excl;
    if (i < NODES) {
        int excl = incl - d + blkoff;
        g_rowptr[i] = excl;
        g_cursor[i] = excl;
        g_nsrc[i] = rsqrtf((float)max(g_degout[i], 1));
        g_ndst[i] = rsqrtf((float)max(d, 1));
    }
}

// ---------------- kernel 3: fill CSR edge lists (4 edges/thread) ----------------
__global__ void k_fill(const int* __restrict__ src, const int* __restrict__ dst) {
    int idx = blockIdx.x * blockDim.x + threadIdx.x;
    if (idx < NEDGES / 4) {
        int4 s = __ldg((const int4*)src + idx);
        int4 d = __ldg((const int4*)dst + idx);
        int p0 = atomicAdd(&g_cursor[d.x], 1);
        int p1 = atomicAdd(&g_cursor[d.y], 1);
        int p2 = atomicAdd(&g_cursor[d.z], 1);
        int p3 = atomicAdd(&g_cursor[d.w], 1);
        g_esrc[p0] = s.x;
        g_esrc[p1] = s.y;
        g_esrc[p2] = s.z;
        g_esrc[p3] = s.w;
    }
}

// ---------------- kernel 4: gather (warp per node, 4-deep MLP) ----------------
__global__ void k_gather(const float* __restrict__ X) {
    int w    = (blockIdx.x * blockDim.x + threadIdx.x) >> 5;
    int lane = threadIdx.x & 31;
    if (w >= NODES) return;
    int beg = g_rowptr[w];
    int cnt = g_degin[w];
    float4 a = make_float4(0.f, 0.f, 0.f, 0.f);
    int i = 0;
    for (; i + 3 < cnt; i += 4) {
        int s0 = __ldg(g_esrc + beg + i);
        int s1 = __ldg(g_esrc + beg + i + 1);
        int s2 = __ldg(g_esrc + beg + i + 2);
        int s3 = __ldg(g_esrc + beg + i + 3);
        float c0 = __ldg(g_nsrc + s0);
        float c1 = __ldg(g_nsrc + s1);
        float c2 = __ldg(g_nsrc + s2);
        float c3 = __ldg(g_nsrc + s3);
        float4 v0 = __ldg((const float4*)(X + (size_t)s0 * DD) + lane);
        float4 v1 = __ldg((const float4*)(X + (size_t)s1 * DD) + lane);
        float4 v2 = __ldg((const float4*)(X + (size_t)s2 * DD) + lane);
        float4 v3 = __ldg((const float4*)(X + (size_t)s3 * DD) + lane);
        a.x += v0.x * c0 + v1.x * c1 + v2.x * c2 + v3.x * c3;
        a.y += v0.y * c0 + v1.y * c1 + v2.y * c2 + v3.y * c3;
        a.z += v0.z * c0 + v1.z * c1 + v2.z * c2 + v3.z * c3;
        a.w += v0.w * c0 + v1.w * c1 + v2.w * c2 + v3.w * c3;
    }
    for (; i < cnt; i++) {
        int s0 = __ldg(g_esrc + beg + i);
        float c0 = __ldg(g_nsrc + s0);
        float4 v0 = __ldg((const float4*)(X + (size_t)s0 * DD) + lane);
        a.x += v0.x * c0; a.y += v0.y * c0; a.z += v0.z * c0; a.w += v0.w * c0;
    }
    float nd = g_ndst[w];
    a.x *= nd; a.y *= nd; a.z *= nd; a.w *= nd;
    *((float4*)(g_agg + (size_t)w * DD) + lane) = a;
}

// ---------------- GEMM staging (512 threads) ----------------
// B smem layout: [n][k2] with row stride BPAD2 (n-major, ldmatrix-friendly)
__device__ __forceinline__ void stageB(int mat, uint32_t* __restrict__ bhi,
                                       uint32_t* __restrict__ blo, int tid) {
    #pragma unroll
    for (int it = 0; it < 4; it++) {
        int idx = tid + it * 512;          // 2048 uint4 per half
        int n = idx >> 4, c = idx & 15;
        uint4 h = __ldg((const uint4*)(g_bhi[mat]) + n * 16 + c);
        uint4 l = __ldg((const uint4*)(g_blo[mat]) + n * 16 + c);
        *(uint4*)(bhi + n * BPAD2 + c * 4) = h;
        *(uint4*)(blo + n * BPAD2 + c * 4) = l;
    }
}

__device__ __forceinline__ void ldA(const float* __restrict__ srcA, int m0, int tid,
                                    int kc, float4* a_pf) {
    int m = tid >> 2, kw4 = tid & 3;
    int gm = m0 + m;
    int k = kc * 32 + kw4 * 8;
    if (gm < NODES) {
        a_pf[0] = __ldg((const float4*)(srcA + (size_t)gm * DD + k));
        a_pf[1] = __ldg((const float4*)(srcA + (size_t)gm * DD + k + 4));
    } else {
        a_pf[0] = make_float4(0.f, 0.f, 0.f, 0.f);
        a_pf[1] = make_float4(0.f, 0.f, 0.f, 0.f);
    }
}

__device__ __forceinline__ void stA(uint32_t* __restrict__ ahi, uint32_t* __restrict__ alo,
                                    int tid, const float4* a_pf) {
    int m = tid >> 2, kw4 = tid & 3;
    float4 f0 = a_pf[0], f1 = a_pf[1];
    uint32_t h0, l0, h1, l1, h2, l2, h3, l3;
    bpack(f0.x, f0.y, h0, l0);
    bpack(f0.z, f0.w, h1, l1);
    bpack(f1.x, f1.y, h2, l2);
    bpack(f1.z, f1.w, h3, l3);
    uint32_t* ph = ahi + m * APADW + kw4 * 4;
    uint32_t* pl = alo + m * APADW + kw4 * 4;
    ph[0] = h0; ph[1] = h1; ph[2] = h2; ph[3] = h3;
    pl[0] = l0; pl[1] = l1; pl[2] = l2; pl[3] = l3;
}

// ---------------- one GEMM phase: acc += srcA[m0:m0+128, :] @ B[mat] (3xBF16, ldmatrix) ----------------
__device__ __forceinline__ void run_phase(const float* __restrict__ srcA, int mat,
                                          uint32_t* __restrict__ smw, int m0, int tid,
                                          float acc[2][4][4]) {
    const int lane = tid & 31, wid = tid >> 5;
    const int wm = (wid >> 2) * 32;
    const int wn = (wid & 3) * 32;

    stageB(mat, smw + W_BHI, smw + W_BLO, tid);

    float4 a_pf[2];
    ldA(srcA, m0, tid, 0, a_pf);

    uint32_t sbase = (uint32_t)__cvta_generic_to_shared(smw);
    // A: tile = lane>>3 -> (row+8 if bit0, khalf if bit1)
    uint32_t aoff = (((lane & 7) + ((lane >> 3) & 1) * 8) * APADW + ((lane >> 4) & 1) * 4) * 4;
    // B: tiles ordered (nt_lo kh0, nt_lo kh1, nt_hi kh0, nt_hi kh1)
    uint32_t boff = ((((lane >> 4) & 1) * 8 + (lane & 7)) * BPAD2 + ((lane >> 3) & 1) * 4) * 4;
    uint32_t bb_hi = sbase + (uint32_t)(wn * BPAD2) * 4 + boff;   // W_BHI = 0
    uint32_t bb_lo = bb_hi + W_BLO * 4;

    #pragma unroll 1
    for (int kc = 0; kc < 4; kc++) {
        uint32_t* Ahi = smw + W_A0 + (kc & 1) * ABUF_W;
        uint32_t* Alo = Ahi + 2560;
        stA(Ahi, Alo, tid, a_pf);
        __syncthreads();
        if (kc < 3) ldA(srcA, m0, tid, kc + 1, a_pf);

        uint32_t ab_hi = sbase + (uint32_t)(W_A0 + (kc & 1) * ABUF_W + wm * APADW) * 4 + aoff;
        uint32_t ab_lo = ab_hi + 2560 * 4;

        #pragma unroll
        for (int ls = 0; ls < 2; ls++) {
            uint32_t ah[2][4], al[2][4], bh[4][2], bl[4][2];
            #pragma unroll
            for (int mt = 0; mt < 2; mt++) {
                uint32_t d1 = (uint32_t)(mt * 16 * APADW + ls * 8) * 4;
                LDSM_X4(ah[mt][0], ah[mt][1], ah[mt][2], ah[mt][3], ab_hi + d1);
                LDSM_X4(al[mt][0], al[mt][1], al[mt][2], al[mt][3], ab_lo + d1);
            }
            uint32_t bkb = (uint32_t)((kc * 16 + ls * 8) * 4);
            #pragma unroll
            for (int p = 0; p < 2; p++) {
                uint32_t d2 = (uint32_t)(p * 16 * BPAD2) * 4 + bkb;
                LDSM_X4(bh[2*p][0], bh[2*p][1], bh[2*p+1][0], bh[2*p+1][1], bb_hi + d2);
                LDSM_X4(bl[2*p][0], bl[2*p][1], bl[2*p+1][0], bl[2*p+1][1], bb_lo + d2);
            }
            #pragma unroll
            for (int mt = 0; mt < 2; mt++)
                #pragma unroll
                for (int nt = 0; nt < 4; nt++) {
                    mma_bf16(acc[mt][nt], ah[mt], bh[nt]);
                    mma_bf16(acc[mt][nt], al[mt], bh[nt]);
                    mma_bf16(acc[mt][nt], ah[mt], bl[nt]);
                }
        }
        __syncthreads();
    }
}

// ---------------- kernel 5: bf16 mma dual GEMM + fused BN stats (512 thr) ----------------
__global__ void __launch_bounds__(512, 1)
k_gemm_mma(const float* __restrict__ X) {
    extern __shared__ uint32_t smw[];
    const int tid = threadIdx.x;
    const int m0 = blockIdx.x * BM;
    const int lane = tid & 31, wid = tid >> 5;
    const int wm = (wid >> 2) * 32, wn = (wid & 3) * 32;
    const int gr = lane >> 2, kq = lane & 3;
    float* keep = (float*)(smw + W_KEEP);

    float acc[2][4][4];

    // ---- phase 1: residual X @ Wres (mat 0) ----
    #pragma unroll
    for (int mt = 0; mt < 2; mt++)
        #pragma unroll
        for (int nt = 0; nt < 4; nt++)
            #pragma unroll
            for (int q = 0; q < 4; q++) acc[mt][nt][q] = 0.f;
    run_phase(X, 0, smw, m0, tid, acc);

    #pragma unroll
    for (int mt = 0; mt < 2; mt++) {
        int r0 = wm + mt * 16 + gr;
        int r1 = r0 + 8;
        #pragma unroll
        for (int nt = 0; nt < 4; nt++) {
            int c = wn + nt * 8 + kq * 2;
            *(float2*)(keep + r0 * KSTR + c) =
                make_float2(fmaxf(acc[mt][nt][0], 0.f), fmaxf(acc[mt][nt][1], 0.f));
            *(float2*)(keep + r1 * KSTR + c) =
                make_float2(fmaxf(acc[mt][nt][2], 0.f), fmaxf(acc[mt][nt][3], 0.f));
            #pragma unroll
            for (int q = 0; q < 4; q++) acc[mt][nt][q] = 0.f;
        }
    }

    // ---- phase 2: conv agg @ W (mat 1); norm_dst folded into g_agg ----
    run_phase(g_agg, 1, smw, m0, tid, acc);

    // ---- epilogue ----
    float cs[8], cq[8];
    #pragma unroll
    for (int j = 0; j < 8; j++) { cs[j] = 0.f; cq[j] = 0.f; }

    #pragma unroll
    for (int mt = 0; mt < 2; mt++) {
        int lr0 = wm + mt * 16 + gr;
        int lr1 = lr0 + 8;
        int r0 = m0 + lr0, r1 = m0 + lr1;
        #pragma unroll
        for (int nt = 0; nt < 4; nt++) {
            int c = wn + nt * 8 + kq * 2;
            float2 k0 = *(float2*)(keep + lr0 * KSTR + c);
            float2 k1 = *(float2*)(keep + lr1 * KSTR + c);
            float v0 = k0.x + fmaxf(acc[mt][nt][0], 0.f);
            float v1 = k0.y + fmaxf(acc[mt][nt][1], 0.f);
            float v2 = k1.x + fmaxf(acc[mt][nt][2], 0.f);
            float v3 = k1.y + fmaxf(acc[mt][nt][3], 0.f);
            if (r0 < NODES) *(float2*)(g_gX + (size_t)r0 * DD + c) = make_float2(v0, v1);
            if (r1 < NODES) *(float2*)(g_gX + (size_t)r1 * DD + c) = make_float2(v2, v3);
            if (r0 >= NODES) { v0 = 0.f; v1 = 0.f; }
            if (r1 >= NODES) { v2 = 0.f; v3 = 0.f; }
            cs[2 * nt + 0] += v0 + v2;
            cs[2 * nt + 1] += v1 + v3;
            cq[2 * nt + 0] += v0 * v0 + v2 * v2;
            cq[2 * nt + 1] += v1 * v1 + v3 * v3;
        }
    }

    #pragma unroll
    for (int j = 0; j < 8; j++) {
        #pragma unroll
        for (int off = 16; off >= 4; off >>= 1) {
            cs[j] += __shfl_xor_sync(0xFFFFFFFF, cs[j], off);
            cq[j] += __shfl_xor_sync(0xFFFFFFFF, cq[j], off);
        }
    }

    __syncthreads();
    float* redsum = (float*)(smw + W_A0);
    float* redsq  = redsum + 128;
    if (tid < 128) { redsum[tid] = 0.f; redsq[tid] = 0.f; }
    __syncthreads();
    if (gr == 0) {
        #pragma unroll
        for (int j = 0; j < 8; j++) {
            int c = wn + (j >> 1) * 8 + kq * 2 + (j & 1);
            atomicAdd(&redsum[c], cs[j]);
            atomicAdd(&redsq[c], cq[j]);
        }
    }
    __syncthreads();
    if (tid < 128) {
        atomicAdd(&g_sum[tid], redsum[tid]);
        atomicAdd(&g_sumsq[tid], redsq[tid]);
    }
}

// ---------------- kernel 6: finalize (per-block) + apply BN ----------------
__global__ void k_bn(const float* __restrict__ gamma, const float* __restrict__ beta,
                     float* __restrict__ out) {
    __shared__ float sc[DD], bi[DD];
    int t = threadIdx.x;
    if (t < DD) {
        const float invN = 1.f / (float)NODES;
        float mean = g_sum[t] * invN;
        float var  = fmaxf(g_sumsq[t] * invN - mean * mean, 0.f);
        float inv  = rsqrtf(var + BN_EPS);
        float s = __ldg(gamma + t) * inv;
        sc[t] = s;
        bi[t] = __ldg(beta + t) - s * mean;
    }
    __syncthreads();
    int i = blockIdx.x * blockDim.x + t;
    if (i >= NODES * DD / 4) return;
    int c4 = i & 31;
    float4 s4 = ((const float4*)sc)[c4];
    float4 b4 = ((const float4*)bi)[c4];
    float4 v  = ((const float4*)g_gX)[i];
    float4 o;
    o.x = fmaf(v.x, s4.x, b4.x);
    o.y = fmaf(v.y, s4.y, b4.y);
    o.z = fmaf(v.z, s4.z, b4.z);
    o.w = fmaf(v.w, s4.w, b4.w);
    ((float4*)out)[i] = o;
}

// ---------------- launch ----------------
extern "C" void kernel_launch(void* const* d_in, const int* in_sizes, int n_in,
                              void* d_out, int out_size) {
    const float* X     = (const float*)d_in[0];
    const float* W     = (const float*)d_in[1];
    const float* Wres  = (const float*)d_in[2];
    const float* gamma = (const float*)d_in[3];
    const float* beta  = (const float*)d_in[4];
    const int*   src   = (const int*)d_in[5];
    const int*   dst   = (const int*)d_in[6];
    float* out = (float*)d_out;

    (void)in_sizes; (void)n_in; (void)out_size;

    cudaFuncSetAttribute(k_gemm_mma, cudaFuncAttributeMaxDynamicSharedMemorySize, SMEM_BYTES);

    k_initprep<<<113, 256>>>(W, Wres);
    k_deg<<<(NEDGES / 4 + 255) / 256, 256>>>(src, dst);
    k_scan<<<NBLK, 256>>>();
    k_fill<<<(NEDGES / 4 + 255) / 256, 256>>>(src, dst);
    k_gather<<<(NODES * 32 + 255) / 256, 256>>>(X);
    k_gemm_mma<<<(NODES + BM - 1) / BM, 512, SMEM_BYTES>>>(X);
    k_bn<<<(NODES * DD / 4 + 255) / 256, 256>>>(gamma, beta, out);
}

// round 17
// speedup vs baseline: 1.0333x; 1.0333x over previous
#include <cuda_runtime.h>
#include <cuda_bf16.h>
#include <cstdint>

#define NODES  50000
#define NEDGES 600000
#define DD     128
#define BM     128
#define BN_EPS 1e-5f
#define NBLK   ((NODES + 255) / 256)   // 196

// ---------------- scratch (no allocations allowed) ----------------
__device__ __align__(16) float g_agg[NODES * DD];   // fully written by gather
__device__ __align__(16) float g_gX[NODES * DD];
__device__ int   g_degout[NODES];   // zeroed by k_bn tail of previous replay (BSS-zero first run)
__device__ int   g_degin[NODES];
__device__ int   g_rowptr[NODES];
__device__ int   g_cursor[NODES];
__device__ int   g_esrc[NEDGES];
__device__ int   g_blksum[NBLK];
__device__ float g_nsrc[NODES];
__device__ float g_ndst[NODES];
__device__ float g_sum[DD];
__device__ float g_sumsq[DD];
// pre-split B matrices: [mat][k2*128+n] packed bf16x2 (lo half = k-even)
__device__ __align__(16) uint32_t g_bhi[2][8192];
__device__ __align__(16) uint32_t g_blo[2][8192];

// ---------------- bf16 split helpers (integer RNE, no cvt pipe) ----------------
__device__ __forceinline__ uint32_t bf16_hi_bits(float x) {
    uint32_t b = __float_as_uint(x);
    return (b + 0x7FFFu + ((b >> 16) & 1u)) & 0xFFFF0000u;
}
__device__ __forceinline__ void bpack(float ve, float vo, uint32_t& whi, uint32_t& wlo) {
    uint32_t he = bf16_hi_bits(ve), ho = bf16_hi_bits(vo);
    float re = ve - __uint_as_float(he);
    float ro = vo - __uint_as_float(ho);
    uint32_t le = bf16_hi_bits(re), lo = bf16_hi_bits(ro);
    whi = ho | (he >> 16);
    wlo = lo | (le >> 16);
}

__device__ __forceinline__ void mma_bf16(float* d, const uint32_t* a, const uint32_t* b) {
    asm volatile("mma.sync.aligned.m16n8k16.row.col.f32.bf16.bf16.f32 "
        "{%0,%1,%2,%3}, {%4,%5,%6,%7}, {%8,%9}, {%0,%1,%2,%3};"
        : "+f"(d[0]), "+f"(d[1]), "+f"(d[2]), "+f"(d[3])
        : "r"(a[0]), "r"(a[1]), "r"(a[2]), "r"(a[3]), "r"(b[0]), "r"(b[1]));
}

// warp-inclusive scan
__device__ __forceinline__ int wscan(int v, int lane) {
    #pragma unroll
    for (int off = 1; off < 32; off <<= 1) {
        int u = __shfl_up_sync(0xFFFFFFFF, v, off);
        if (lane >= off) v += u;
    }
    return v;
}

// smem word offsets (GEMM kernel)
#define BPADW 136
#define APADW 20
#define KSTR  132
#define W_BHI 0
#define W_BLO 8704
#define W_A0  17408
#define ABUF_W 5120
#define W_KEEP 27648
#define SMEM_WORDS 44544
#define SMEM_BYTES (SMEM_WORDS * 4)   // 178176

// ---------------- kernel 0: pre-split B + zero BN accumulators ----------------
// blocks [0,64): prepB; block 64: zero g_sum/g_sumsq
__global__ void k_initprep(const float* __restrict__ W, const float* __restrict__ Wres) {
    int b = blockIdx.x;
    int t = threadIdx.x;
    if (b < 64) {
        int idx = b * 256 + t;              // 0..16383
        int mat = idx >> 13;
        int r = idx & 8191;
        int k2 = r >> 7, n = r & 127;
        const float* B = mat ? W : Wres;
        float ve = __ldg(B + (size_t)(2 * k2) * DD + n);
        float vo = __ldg(B + (size_t)(2 * k2 + 1) * DD + n);
        uint32_t h, l;
        bpack(ve, vo, h, l);
        g_bhi[mat][r] = h;
        g_blo[mat][r] = l;
    } else {
        if (t < DD) { g_sum[t] = 0.f; g_sumsq[t] = 0.f; }
    }
}

// ---------------- kernel 1: degrees (8 edges/thread, 2x int4 loads) ----------------
__global__ void k_deg(const int* __restrict__ src, const int* __restrict__ dst) {
    int idx = blockIdx.x * blockDim.x + threadIdx.x;
    if (idx < NEDGES / 8) {
        int4 s0 = __ldg((const int4*)src + 2 * idx);
        int4 s1 = __ldg((const int4*)src + 2 * idx + 1);
        int4 d0 = __ldg((const int4*)dst + 2 * idx);
        int4 d1 = __ldg((const int4*)dst + 2 * idx + 1);
        atomicAdd(&g_degout[s0.x], 1);
        atomicAdd(&g_degout[s0.y], 1);
        atomicAdd(&g_degout[s0.z], 1);
        atomicAdd(&g_degout[s0.w], 1);
        atomicAdd(&g_degout[s1.x], 1);
        atomicAdd(&g_degout[s1.y], 1);
        atomicAdd(&g_degout[s1.z], 1);
        atomicAdd(&g_degout[s1.w], 1);
        atomicAdd(&g_degin[d0.x], 1);
        atomicAdd(&g_degin[d0.y], 1);
        atomicAdd(&g_degin[d0.z], 1);
        atomicAdd(&g_degin[d0.w], 1);
        atomicAdd(&g_degin[d1.x], 1);
        atomicAdd(&g_degin[d1.y], 1);
        atomicAdd(&g_degin[d1.z], 1);
        atomicAdd(&g_degin[d1.w], 1);
    }
}

// ---------------- scan stage 1: per-block sums (196 x 256) ----------------
__global__ void k_scan1() {
    __shared__ int ws[8];
    int t = threadIdx.x, lane = t & 31, wid = t >> 5;
    int i = blockIdx.x * 256 + t;
    int v = (i < NODES) ? g_degin[i] : 0;
    #pragma unroll
    for (int off = 16; off > 0; off >>= 1)
        v += __shfl_xor_sync(0xFFFFFFFF, v, off);
    if (lane == 0) ws[wid] = v;
    __syncthreads();
    if (t < 8) {
        int s = ws[t];
        #pragma unroll
        for (int off = 4; off > 0; off >>= 1)
            s += __shfl_xor_sync(0xFF, s, off);
        if (t == 0) g_blksum[blockIdx.x] = s;
    }
}

// ---------------- scan stage 2 (fused): warp-shuffle scans ----------------
__global__ void k_scan3() {
    __shared__ int bs[256];
    __shared__ int ws[8];
    int t = threadIdx.x, lane = t & 31, wid = t >> 5;

    // scan of the 196 block sums (redundant per block; removes a kernel)
    {
        int v = (t < NBLK) ? g_blksum[t] : 0;
        int w = wscan(v, lane);
        if (lane == 31) ws[wid] = w;
        __syncthreads();
        if (wid == 0) {
            int s = (lane < 8) ? ws[lane] : 0;
            int sw = wscan(s, lane);
            if (lane < 8) ws[lane] = sw;
        }
        __syncthreads();
        bs[t] = w + (wid ? ws[wid - 1] : 0);
        __syncthreads();
    }
    int blkoff = (blockIdx.x == 0) ? 0 : bs[blockIdx.x - 1];
    __syncthreads();   // ws reuse below

    // local scan of this block's 256 degrees
    int i = blockIdx.x * 256 + t;
    int d = (i < NODES) ? g_degin[i] : 0;
    int w = wscan(d, lane);
    if (lane == 31) ws[wid] = w;
    __syncthreads();
    if (wid == 0) {
        int s = (lane < 8) ? ws[lane] : 0;
        int sw = wscan(s, lane);
        if (lane < 8) ws[lane] = sw;
    }
    __syncthreads();
    int incl = w + (wid ? ws[wid - 1] : 0);
    if (i < NODES) {
        int excl = incl - d + blkoff;
        g_rowptr[i] = excl;
        g_cursor[i] = excl;
        g_nsrc[i] = rsqrtf((float)max(g_degout[i], 1));
        g_ndst[i] = rsqrtf((float)max(d, 1));
    }
}

// ---------------- kernel 2a: fill CSR edge lists (8 edges/thread) ----------------
__global__ void k_fill(const int* __restrict__ src, const int* __restrict__ dst) {
    int idx = blockIdx.x * blockDim.x + threadIdx.x;
    if (idx < NEDGES / 8) {
        int4 s0 = __ldg((const int4*)src + 2 * idx);
        int4 s1 = __ldg((const int4*)src + 2 * idx + 1);
        int4 d0 = __ldg((const int4*)dst + 2 * idx);
        int4 d1 = __ldg((const int4*)dst + 2 * idx + 1);
        int p0 = atomicAdd(&g_cursor[d0.x], 1);
        int p1 = atomicAdd(&g_cursor[d0.y], 1);
        int p2 = atomicAdd(&g_cursor[d0.z], 1);
        int p3 = atomicAdd(&g_cursor[d0.w], 1);
        int p4 = atomicAdd(&g_cursor[d1.x], 1);
        int p5 = atomicAdd(&g_cursor[d1.y], 1);
        int p6 = atomicAdd(&g_cursor[d1.z], 1);
        int p7 = atomicAdd(&g_cursor[d1.w], 1);
        g_esrc[p0] = s0.x;
        g_esrc[p1] = s0.y;
        g_esrc[p2] = s0.z;
        g_esrc[p3] = s0.w;
        g_esrc[p4] = s1.x;
        g_esrc[p5] = s1.y;
        g_esrc[p6] = s1.z;
        g_esrc[p7] = s1.w;
    }
}

// ---------------- kernel 2b: gather (warp per node, 4-deep MLP) ----------------
__global__ void k_gather(const float* __restrict__ X) {
    int w    = (blockIdx.x * blockDim.x + threadIdx.x) >> 5;
    int lane = threadIdx.x & 31;
    if (w >= NODES) return;
    int beg = g_rowptr[w];
    int cnt = g_degin[w];
    float4 a = make_float4(0.f, 0.f, 0.f, 0.f);
    int i = 0;
    for (; i + 3 < cnt; i += 4) {
        int s0 = __ldg(g_esrc + beg + i);
        int s1 = __ldg(g_esrc + beg + i + 1);
        int s2 = __ldg(g_esrc + beg + i + 2);
        int s3 = __ldg(g_esrc + beg + i + 3);
        float c0 = __ldg(g_nsrc + s0);
        float c1 = __ldg(g_nsrc + s1);
        float c2 = __ldg(g_nsrc + s2);
        float c3 = __ldg(g_nsrc + s3);
        float4 v0 = __ldg((const float4*)(X + (size_t)s0 * DD) + lane);
        float4 v1 = __ldg((const float4*)(X + (size_t)s1 * DD) + lane);
        float4 v2 = __ldg((const float4*)(X + (size_t)s2 * DD) + lane);
        float4 v3 = __ldg((const float4*)(X + (size_t)s3 * DD) + lane);
        a.x += v0.x * c0 + v1.x * c1 + v2.x * c2 + v3.x * c3;
        a.y += v0.y * c0 + v1.y * c1 + v2.y * c2 + v3.y * c3;
        a.z += v0.z * c0 + v1.z * c1 + v2.z * c2 + v3.z * c3;
        a.w += v0.w * c0 + v1.w * c1 + v2.w * c2 + v3.w * c3;
    }
    for (; i < cnt; i++) {
        int s0 = __ldg(g_esrc + beg + i);
        float c0 = __ldg(g_nsrc + s0);
        float4 v0 = __ldg((const float4*)(X + (size_t)s0 * DD) + lane);
        a.x += v0.x * c0; a.y += v0.y * c0; a.z += v0.z * c0; a.w += v0.w * c0;
    }
    float nd = g_ndst[w];
    a.x *= nd; a.y *= nd; a.z *= nd; a.w *= nd;
    *((float4*)(g_agg + (size_t)w * DD) + lane) = a;
}

// ---------------- GEMM staging (512 threads) ----------------
__device__ __forceinline__ void stageB(int mat, uint32_t* __restrict__ bhi,
                                       uint32_t* __restrict__ blo, int tid) {
    #pragma unroll
    for (int it = 0; it < 4; it++) {
        int idx = tid + it * 512;
        int k2 = idx >> 5, n4 = idx & 31;
        uint4 h = __ldg((const uint4*)(g_bhi[mat] + k2 * 128 + n4 * 4));
        uint4 l = __ldg((const uint4*)(g_blo[mat] + k2 * 128 + n4 * 4));
        *(uint4*)(bhi + k2 * BPADW + n4 * 4) = h;
        *(uint4*)(blo + k2 * BPADW + n4 * 4) = l;
    }
}

__device__ __forceinline__ void ldA(const float* __restrict__ srcA, int m0, int tid,
                                    int kc, float4* a_pf) {
    int m = tid >> 2, kw4 = tid & 3;
    int gm = m0 + m;
    int k = kc * 32 + kw4 * 8;
    if (gm < NODES) {
        a_pf[0] = __ldg((const float4*)(srcA + (size_t)gm * DD + k));
        a_pf[1] = __ldg((const float4*)(srcA + (size_t)gm * DD + k + 4));
    } else {
        a_pf[0] = make_float4(0.f, 0.f, 0.f, 0.f);
        a_pf[1] = make_float4(0.f, 0.f, 0.f, 0.f);
    }
}

__device__ __forceinline__ void stA(uint32_t* __restrict__ ahi, uint32_t* __restrict__ alo,
                                    int tid, const float4* a_pf) {
    int m = tid >> 2, kw4 = tid & 3;
    float4 f0 = a_pf[0], f1 = a_pf[1];
    uint32_t h0, l0, h1, l1, h2, l2, h3, l3;
    bpack(f0.x, f0.y, h0, l0);
    bpack(f0.z, f0.w, h1, l1);
    bpack(f1.x, f1.y, h2, l2);
    bpack(f1.z, f1.w, h3, l3);
    uint32_t* ph = ahi + m * APADW + kw4 * 4;
    uint32_t* pl = alo + m * APADW + kw4 * 4;
    ph[0] = h0; ph[1] = h1; ph[2] = h2; ph[3] = h3;
    pl[0] = l0; pl[1] = l1; pl[2] = l2; pl[3] = l3;
}

// ---------------- one GEMM phase: acc += srcA[m0:m0+128, :] @ B[mat] (3xBF16) ----------------
__device__ __forceinline__ void run_phase(const float* __restrict__ srcA, int mat,
                                          uint32_t* __restrict__ smw, int m0, int tid,
                                          float acc[2][4][4]) {
    uint32_t* Bhi = smw + W_BHI;
    uint32_t* Blo = smw + W_BLO;
    const int lane = tid & 31, wid = tid >> 5;
    const int wm = (wid >> 2) * 32;
    const int wn = (wid & 3) * 32;
    const int gr = lane >> 2, kq = lane & 3;

    stageB(mat, Bhi, Blo, tid);

    float4 a_pf[2];
    ldA(srcA, m0, tid, 0, a_pf);

    #pragma unroll 1
    for (int kc = 0; kc < 4; kc++) {
        uint32_t* Ahi = smw + W_A0 + (kc & 1) * ABUF_W;
        uint32_t* Alo = Ahi + 2560;
        stA(Ahi, Alo, tid, a_pf);
        __syncthreads();
        if (kc < 3) ldA(srcA, m0, tid, kc + 1, a_pf);

        #pragma unroll
        for (int ls = 0; ls < 2; ls++) {
            int ak2 = ls * 8;
            int bk2 = kc * 16 + ls * 8;
            uint32_t ah[2][4], al[2][4], bh[4][2], bl[4][2];
            #pragma unroll
            for (int mt = 0; mt < 2; mt++) {
                int r = wm + mt * 16 + gr;
                const uint32_t* p = Ahi + r * APADW + ak2 + kq;
                const uint32_t* q = Alo + r * APADW + ak2 + kq;
                ah[mt][0] = p[0];
                ah[mt][1] = p[8 * APADW];
                ah[mt][2] = p[4];
                ah[mt][3] = p[8 * APADW + 4];
                al[mt][0] = q[0];
                al[mt][1] = q[8 * APADW];
                al[mt][2] = q[4];
                al[mt][3] = q[8 * APADW + 4];
            }
            #pragma unroll
            for (int nt = 0; nt < 4; nt++) {
                int c = wn + nt * 8 + gr;
                const uint32_t* p = Bhi + (bk2 + kq) * BPADW + c;
                const uint32_t* q = Blo + (bk2 + kq) * BPADW + c;
                bh[nt][0] = p[0];
                bh[nt][1] = p[4 * BPADW];
                bl[nt][0] = q[0];
                bl[nt][1] = q[4 * BPADW];
            }
            #pragma unroll
            for (int mt = 0; mt < 2; mt++)
                #pragma unroll
                for (int nt = 0; nt < 4; nt++) {
                    mma_bf16(acc[mt][nt], ah[mt], bh[nt]);
                    mma_bf16(acc[mt][nt], al[mt], bh[nt]);
                    mma_bf16(acc[mt][nt], ah[mt], bl[nt]);
                }
        }
        __syncthreads();
    }
}

// ---------------- kernel 3: bf16 mma dual GEMM + fused BN stats (512 thr) ----------------
__global__ void __launch_bounds__(512, 1)
k_gemm_mma(const float* __restrict__ X) {
    extern __shared__ uint32_t smw[];
    const int tid = threadIdx.x;
    const int m0 = blockIdx.x * BM;
    const int lane = tid & 31, wid = tid >> 5;
    const int wm = (wid >> 2) * 32, wn = (wid & 3) * 32;
    const int gr = lane >> 2, kq = lane & 3;
    float* keep = (float*)(smw + W_KEEP);

    float acc[2][4][4];

    // ---- phase 1: residual X @ Wres (mat 0) ----
    #pragma unroll
    for (int mt = 0; mt < 2; mt++)
        #pragma unroll
        for (int nt = 0; nt < 4; nt++)
            #pragma unroll
            for (int q = 0; q < 4; q++) acc[mt][nt][q] = 0.f;
    run_phase(X, 0, smw, m0, tid, acc);

    #pragma unroll
    for (int mt = 0; mt < 2; mt++) {
        int r0 = wm + mt * 16 + gr;
        int r1 = r0 + 8;
        #pragma unroll
        for (int nt = 0; nt < 4; nt++) {
            int c = wn + nt * 8 + kq * 2;
            *(float2*)(keep + r0 * KSTR + c) =
                make_float2(fmaxf(acc[mt][nt][0], 0.f), fmaxf(acc[mt][nt][1], 0.f));
            *(float2*)(keep + r1 * KSTR + c) =
                make_float2(fmaxf(acc[mt][nt][2], 0.f), fmaxf(acc[mt][nt][3], 0.f));
            #pragma unroll
            for (int q = 0; q < 4; q++) acc[mt][nt][q] = 0.f;
        }
    }

    // ---- phase 2: conv agg @ W (mat 1); norm_dst already folded into g_agg ----
    run_phase(g_agg, 1, smw, m0, tid, acc);

    // ---- epilogue ----
    float cs[8], cq[8];
    #pragma unroll
    for (int j = 0; j < 8; j++) { cs[j] = 0.f; cq[j] = 0.f; }

    #pragma unroll
    for (int mt = 0; mt < 2; mt++) {
        int lr0 = wm + mt * 16 + gr;
        int lr1 = lr0 + 8;
        int r0 = m0 + lr0, r1 = m0 + lr1;
        #pragma unroll
        for (int nt = 0; nt < 4; nt++) {
            int c = wn + nt * 8 + kq * 2;
            float2 k0 = *(float2*)(keep + lr0 * KSTR + c);
            float2 k1 = *(float2*)(keep + lr1 * KSTR + c);
            float v0 = k0.x + fmaxf(acc[mt][nt][0], 0.f);
            float v1 = k0.y + fmaxf(acc[mt][nt][1], 0.f);
            float v2 = k1.x + fmaxf(acc[mt][nt][2], 0.f);
            float v3 = k1.y + fmaxf(acc[mt][nt][3], 0.f);
            if (r0 < NODES) *(float2*)(g_gX + (size_t)r0 * DD + c) = make_float2(v0, v1);
            if (r1 < NODES) *(float2*)(g_gX + (size_t)r1 * DD + c) = make_float2(v2, v3);
            if (r0 >= NODES) { v0 = 0.f; v1 = 0.f; }
            if (r1 >= NODES) { v2 = 0.f; v3 = 0.f; }
            cs[2 * nt + 0] += v0 + v2;
            cs[2 * nt + 1] += v1 + v3;
            cq[2 * nt + 0] += v0 * v0 + v2 * v2;
            cq[2 * nt + 1] += v1 * v1 + v3 * v3;
        }
    }

    #pragma unroll
    for (int j = 0; j < 8; j++) {
        #pragma unroll
        for (int off = 16; off >= 4; off >>= 1) {
            cs[j] += __shfl_xor_sync(0xFFFFFFFF, cs[j], off);
            cq[j] += __shfl_xor_sync(0xFFFFFFFF, cq[j], off);
        }
    }

    __syncthreads();
    float* redsum = (float*)(smw + W_A0);
    float* redsq  = redsum + 128;
    if (tid < 128) { redsum[tid] = 0.f; redsq[tid] = 0.f; }
    __syncthreads();
    if (gr == 0) {
        #pragma unroll
        for (int j = 0; j < 8; j++) {
            int c = wn + (j >> 1) * 8 + kq * 2 + (j & 1);
            atomicAdd(&redsum[c], cs[j]);
            atomicAdd(&redsq[c], cq[j]);
        }
    }
    __syncthreads();
    if (tid < 128) {
        atomicAdd(&g_sum[tid], redsum[tid]);
        atomicAdd(&g_sumsq[tid], redsq[tid]);
    }
}

// ---------------- kernel 5: finalize (per-block) + apply BN + reset degrees ----------------
__global__ void k_bn(const float* __restrict__ gamma, const float* __restrict__ beta,
                     float* __restrict__ out) {
    __shared__ float sc[DD], bi[DD];
    int t = threadIdx.x;
    if (t < DD) {
        const float invN = 1.f / (float)NODES;
        float mean = g_sum[t] * invN;
        float var  = fmaxf(g_sumsq[t] * invN - mean * mean, 0.f);
        float inv  = rsqrtf(var + BN_EPS);
        float s = __ldg(gamma + t) * inv;
        sc[t] = s;
        bi[t] = __ldg(beta + t) - s * mean;
    }
    __syncthreads();
    int i = blockIdx.x * blockDim.x + t;
    // reset degree arrays for the next graph replay (dead at this point)
    if (i < NODES / 4) {
        ((int4*)g_degout)[i] = make_int4(0, 0, 0, 0);
        ((int4*)g_degin)[i]  = make_int4(0, 0, 0, 0);
    }
    if (i >= NODES * DD / 4) return;
    int c4 = i & 31;
    float4 s4 = ((const float4*)sc)[c4];
    float4 b4 = ((const float4*)bi)[c4];
    float4 v  = ((const float4*)g_gX)[i];
    float4 o;
    o.x = fmaf(v.x, s4.x, b4.x);
    o.y = fmaf(v.y, s4.y, b4.y);
    o.z = fmaf(v.z, s4.z, b4.z);
    o.w = fmaf(v.w, s4.w, b4.w);
    ((float4*)out)[i] = o;
}

// ---------------- launch ----------------
extern "C" void kernel_launch(void* const* d_in, const int* in_sizes, int n_in,
                              void* d_out, int out_size) {
    const float* X     = (const float*)d_in[0];
    const float* W     = (const float*)d_in[1];
    const float* Wres  = (const float*)d_in[2];
    const float* gamma = (const float*)d_in[3];
    const float* beta  = (const float*)d_in[4];
    const int*   src   = (const int*)d_in[5];
    const int*   dst   = (const int*)d_in[6];
    float* out = (float*)d_out;

    (void)in_sizes; (void)n_in; (void)out_size;

    cudaFuncSetAttribute(k_gemm_mma, cudaFuncAttributeMaxDynamicSharedMemorySize, SMEM_BYTES);

    k_initprep<<<65, 256>>>(W, Wres);
    k_deg<<<(NEDGES / 8 + 255) / 256, 256>>>(src, dst);
    k_scan1<<<NBLK, 256>>>();
    k_scan3<<<NBLK, 256>>>();
    k_fill<<<(NEDGES / 8 + 255) / 256, 256>>>(src, dst);
    k_gather<<<(NODES * 32 + 255) / 256, 256>>>(X);
    k_gemm_mma<<<(NODES + BM - 1) / BM, 512, SMEM_BYTES>>>(X);
    k_bn<<<(NODES * DD / 4 + 255) / 256, 256>>>(gamma, beta, out);
}